// round 2
// baseline (speedup 1.0000x reference)
#include <cuda_runtime.h>
#include <math.h>

#define NTH 512

// ---------------- scratch globals (no allocations allowed) ----------------
__device__ float g_pstats[128][20];   // per-image per-channel [sum(10), sumsq(10)]
__device__ float g_qsel[128][10];     // q gathered at (S1,S2) per image

// ---------------- shared memory layout (floats) ----------------
static constexpr int SZ_XP  = 2 * 68 * 68;   // X padded by 2
static constexpr int SZ_X1P = 2 * 36 * 36;   // maxpooled X padded by 2
static constexpr int SZ_R1P = 34 * 34;       // r1 padded by 1
static constexpr int SZ_VS  = 34 * 34;       // small v ping/pong
static constexpr int SZ_SA  = 32 * 32;       // small s accum
static constexpr int SZ_BIG = 66 * 66;       // 64x64 padded by 1
static constexpr int SZ_SB  = 64 * 64;       // big s accum
static constexpr int SZ_W5  = 9 * 2 * 25;    // 9 boundary variants of composed 5x5
static constexpr int SZ_TMP = 162;           // composed-weight scratch
static constexpr int SZ_WQ  = 16 * 10 * 27;  // conv_q_ws
static constexpr int SZ_WQV = 16 * 10 * 18;  // vi_conv_q_ws
static constexpr int SZ_RED = 16 * 20;       // block reduction

static constexpr int OFF_XP   = 0;
static constexpr int OFF_X1P  = OFF_XP   + SZ_XP;
static constexpr int OFF_R1P  = OFF_X1P  + SZ_X1P;
static constexpr int OFF_VSA  = OFF_R1P  + SZ_R1P;
static constexpr int OFF_VSB  = OFF_VSA  + SZ_VS;
static constexpr int OFF_SA   = OFF_VSB  + SZ_VS;
static constexpr int OFF_MP   = OFF_SA   + SZ_SA;
static constexpr int OFF_RP   = OFF_MP   + SZ_BIG;
static constexpr int OFF_VA   = OFF_RP   + SZ_BIG;
static constexpr int OFF_VB   = OFF_VA   + SZ_BIG;
static constexpr int OFF_SB   = OFF_VB   + SZ_BIG;
static constexpr int OFF_W5M  = OFF_SB   + SZ_SB;
static constexpr int OFF_W5V  = OFF_W5M  + SZ_W5;
static constexpr int OFF_TMPW = OFF_W5V  + SZ_W5;
static constexpr int OFF_WQ   = OFF_TMPW + SZ_TMP;
static constexpr int OFF_WQV  = OFF_WQ   + SZ_WQ;
static constexpr int OFF_REDU = OFF_WQV  + SZ_WQV;
static constexpr int TOTAL_F  = OFF_REDU + SZ_RED;
static constexpr int SMEM_BYTES = TOTAL_F * 4;   // ~186 KB < 227 KB

// Build one boundary-variant composed 5x5 kernel entry from tmpw.
// tmpw[((a*3+b)*2+ii)*9 + p*3+q] = sum_h Wr[h][a][b] * Wh[h][ii][p][q]
__device__ __forceinline__ float build_w5_entry(const float* tmpw, int e) {
    int v  = e % 5;
    int u  = (e / 5) % 5;
    int ii = (e / 25) % 2;
    int cx = (e / 50) % 3;
    int cy = e / 150;
    float acc = 0.f;
    for (int a = 0; a < 3; ++a) {
        if ((cy == 0 && a == 0) || (cy == 2 && a == 2)) continue;  // clip h rows
        for (int b = 0; b < 3; ++b) {
            if ((cx == 0 && b == 0) || (cx == 2 && b == 2)) continue;
            int p = u - a, q = v - b;
            if (p < 0 || p > 2 || q < 0 || q > 2) continue;
            acc += tmpw[((a * 3 + b) * 2 + ii) * 9 + p * 3 + q];
        }
    }
    return acc;
}

__global__ void __launch_bounds__(NTH, 1)
vin_main_kernel(const float* __restrict__ X,
                const int*   __restrict__ S1,
                const int*   __restrict__ S2,
                const float* __restrict__ Wh,    // (150,2,3,3)
                const float* __restrict__ Wr,    // (1,150,3,3)
                const float* __restrict__ Wq,    // (16,10,3,3,3)
                const float* __restrict__ Whv,   // (150,2,3,3)
                const float* __restrict__ Wrv,   // (1,150,3,3)
                const float* __restrict__ Wqv)   // (16,10,2,3,3)
{
    extern __shared__ float sm[];
    float* Xp   = sm + OFF_XP;
    float* X1p  = sm + OFF_X1P;
    float* r1p  = sm + OFF_R1P;
    float* vsA  = sm + OFF_VSA;
    float* vsB  = sm + OFF_VSB;
    float* sA   = sm + OFF_SA;
    float* mp   = sm + OFF_MP;
    float* rp   = sm + OFF_RP;
    float* vA   = sm + OFF_VA;
    float* vB   = sm + OFF_VB;
    float* sB   = sm + OFF_SB;
    float* W5m  = sm + OFF_W5M;
    float* W5v  = sm + OFF_W5V;
    float* tmpw = sm + OFF_TMPW;
    float* Wqs  = sm + OFF_WQ;
    float* Wqvs = sm + OFF_WQV;
    float* red  = sm + OFF_REDU;

    const int tid = threadIdx.x;
    const int n   = blockIdx.x;

    // P0: zero all smem (gives us zero padding borders + zero accumulators)
    for (int i = tid; i < TOTAL_F; i += NTH) sm[i] = 0.0f;
    __syncthreads();

    // P1: load X (padded by 2), VI weights, and composed-weight scratch for vi set
    const float* Xn = X + (size_t)n * (2 * 64 * 64);
    for (int i = tid; i < 2 * 64 * 64; i += NTH) {
        int ch = i >> 12, y = (i >> 6) & 63, x = i & 63;
        Xp[ch * (68 * 68) + (y + 2) * 68 + (x + 2)] = Xn[i];
    }
    for (int i = tid; i < SZ_WQ;  i += NTH) Wqs[i]  = Wq[i];
    for (int i = tid; i < SZ_WQV; i += NTH) Wqvs[i] = Wqv[i];
    if (tid < 162) {
        int e = tid;
        int q = e % 3, p = (e / 3) % 3, ii = (e / 9) % 2, b = (e / 18) % 3, a = e / 54;
        float acc = 0.f;
        for (int h = 0; h < 150; ++h)
            acc += Wrv[h * 9 + a * 3 + b] * Whv[(h * 2 + ii) * 9 + p * 3 + q];
        tmpw[e] = acc;
    }
    __syncthreads();

    // P2: build vi composed variants; maxpool X -> X1 (padded by 2)
    if (tid < 450) W5v[tid] = build_w5_entry(tmpw, tid);
    for (int i = tid; i < 2 * 32 * 32; i += NTH) {
        int ch = i >> 10, y = (i >> 5) & 31, x = i & 31;
        const float* b0 = &Xp[ch * (68 * 68) + (2 * y + 2) * 68 + (2 * x + 2)];
        X1p[ch * (36 * 36) + (y + 2) * 36 + (x + 2)] =
            fmaxf(fmaxf(b0[0], b0[1]), fmaxf(b0[68], b0[69]));
    }
    __syncthreads();

    // P3: r1 = composed conv(X1); recompute tmpw for main set
    for (int i = tid; i < 32 * 32; i += NTH) {
        int y = i >> 5, x = i & 31;
        int cy = (y == 0) ? 0 : (y == 31) ? 2 : 1;
        int cx = (x == 0) ? 0 : (x == 31) ? 2 : 1;
        const float* w = &W5v[(cy * 3 + cx) * 50];
        float acc = 0.f;
        #pragma unroll
        for (int ii = 0; ii < 2; ++ii)
            #pragma unroll
            for (int u = 0; u < 5; ++u)
                #pragma unroll
                for (int v = 0; v < 5; ++v)
                    acc += w[ii * 25 + u * 5 + v] * X1p[ii * (36 * 36) + (y + u) * 36 + (x + v)];
        r1p[(y + 1) * 34 + (x + 1)] = acc;
    }
    if (tid < 162) {
        int e = tid;
        int q = e % 3, p = (e / 3) % 3, ii = (e / 9) % 2, b = (e / 18) % 3, a = e / 54;
        float acc = 0.f;
        for (int h = 0; h < 150; ++h)
            acc += Wr[h * 9 + a * 3 + b] * Wh[(h * 2 + ii) * 9 + p * 3 + q];
        tmpw[e] = acc;
    }
    __syncthreads();

    // P4: build main composed variants
    if (tid < 450) W5m[tid] = build_w5_entry(tmpw, tid);
    __syncthreads();

    // P5: small VI loop (32x32, inputs r1 + v, 16 iterations, v = max over 10 ch)
    float r1n[3][6];
    const int srow = tid >> 3;        // valid for tid<256: 0..31
    const int sc0  = (tid & 7) * 4;   // 0..28
    if (tid < 256) {
        #pragma unroll
        for (int dy = 0; dy < 3; ++dy)
            #pragma unroll
            for (int dx = 0; dx < 6; ++dx)
                r1n[dy][dx] = r1p[(srow + dy) * 34 + sc0 + dx];
    }
    for (int k = 0; k < 16; ++k) {
        float* vcur = (k & 1) ? vsB : vsA;
        float* vnxt = (k & 1) ? vsA : vsB;
        if (tid < 256) {
            float av[3][6];
            #pragma unroll
            for (int dy = 0; dy < 3; ++dy)
                #pragma unroll
                for (int dx = 0; dx < 6; ++dx)
                    av[dy][dx] = vcur[(srow + dy) * 34 + sc0 + dx];
            float vm0 = -1e30f, vm1 = -1e30f, vm2 = -1e30f, vm3 = -1e30f;
            const float* wk = &Wqvs[k * 180];
            for (int c = 0; c < 10; ++c) {
                const float* wc = wk + c * 18;
                float q0 = 0.f, q1 = 0.f, q2 = 0.f, q3 = 0.f;
                #pragma unroll
                for (int dy = 0; dy < 3; ++dy)
                    #pragma unroll
                    for (int dx = 0; dx < 3; ++dx) {
                        float w0 = wc[dy * 3 + dx];
                        float w1 = wc[9 + dy * 3 + dx];
                        q0 += w0 * r1n[dy][dx + 0] + w1 * av[dy][dx + 0];
                        q1 += w0 * r1n[dy][dx + 1] + w1 * av[dy][dx + 1];
                        q2 += w0 * r1n[dy][dx + 2] + w1 * av[dy][dx + 2];
                        q3 += w0 * r1n[dy][dx + 3] + w1 * av[dy][dx + 3];
                    }
                vm0 = fmaxf(vm0, q0); vm1 = fmaxf(vm1, q1);
                vm2 = fmaxf(vm2, q2); vm3 = fmaxf(vm3, q3);
            }
            vnxt[(srow + 1) * 34 + sc0 + 1] = vm0;
            vnxt[(srow + 1) * 34 + sc0 + 2] = vm1;
            vnxt[(srow + 1) * 34 + sc0 + 3] = vm2;
            vnxt[(srow + 1) * 34 + sc0 + 4] = vm3;
            sA[srow * 32 + sc0 + 0] += vm0;
            sA[srow * 32 + sc0 + 1] += vm1;
            sA[srow * 32 + sc0 + 2] += vm2;
            sA[srow * 32 + sc0 + 3] += vm3;
        }
        __syncthreads();
    }

    // P6: m = bilinear-upsample(sA/4) into padded mp; r = composed conv(X) into padded rp
    for (int i = tid; i < 64 * 64; i += NTH) {
        int yo = i >> 6, xo = i & 63;
        int jy = yo >> 1, jx = xo >> 1;
        int y0, y1, x0, x1; float wy0, wy1, wx0, wx1;
        if (yo & 1) { y0 = jy; y1 = (jy < 31) ? jy + 1 : 31; wy0 = 0.75f; wy1 = 0.25f; }
        else        { y0 = (jy > 0) ? jy - 1 : 0; y1 = jy;   wy0 = 0.25f; wy1 = 0.75f; }
        if (xo & 1) { x0 = jx; x1 = (jx < 31) ? jx + 1 : 31; wx0 = 0.75f; wx1 = 0.25f; }
        else        { x0 = (jx > 0) ? jx - 1 : 0; x1 = jx;   wx0 = 0.25f; wx1 = 0.75f; }
        float val = wy0 * (wx0 * sA[y0 * 32 + x0] + wx1 * sA[y0 * 32 + x1])
                  + wy1 * (wx0 * sA[y1 * 32 + x0] + wx1 * sA[y1 * 32 + x1]);
        mp[(yo + 1) * 66 + xo + 1] = val * 0.25f;   // denom 4.0
    }
    for (int i = tid; i < 64 * 64; i += NTH) {
        int y = i >> 6, x = i & 63;
        int cy = (y == 0) ? 0 : (y == 63) ? 2 : 1;
        int cx = (x == 0) ? 0 : (x == 63) ? 2 : 1;
        const float* w = &W5m[(cy * 3 + cx) * 50];
        float acc = 0.f;
        #pragma unroll
        for (int ii = 0; ii < 2; ++ii)
            #pragma unroll
            for (int u = 0; u < 5; ++u)
                #pragma unroll
                for (int v = 0; v < 5; ++v)
                    acc += w[ii * 25 + u * 5 + v] * Xp[ii * (68 * 68) + (y + u) * 68 + (x + v)];
        rp[(y + 1) * 66 + (x + 1)] = acc;
    }
    __syncthreads();

    // P7: big VI loop (64x64, inputs m, r, v; 16 iterations)
    const int brow = tid >> 3;        // 0..63
    const int bc0  = (tid & 7) * 8;   // 0..56
    float am[3][10], ar[3][10];
    #pragma unroll
    for (int dy = 0; dy < 3; ++dy)
        #pragma unroll
        for (int dx = 0; dx < 10; ++dx) {
            am[dy][dx] = mp[(brow + dy) * 66 + bc0 + dx];
            ar[dy][dx] = rp[(brow + dy) * 66 + bc0 + dx];
        }
    for (int k = 0; k < 16; ++k) {
        float* vcur = (k & 1) ? vB : vA;
        float* vnxt = (k & 1) ? vA : vB;
        float av[3][10];
        #pragma unroll
        for (int dy = 0; dy < 3; ++dy)
            #pragma unroll
            for (int dx = 0; dx < 10; ++dx)
                av[dy][dx] = vcur[(brow + dy) * 66 + bc0 + dx];
        float vm[8];
        #pragma unroll
        for (int j = 0; j < 8; ++j) vm[j] = -1e30f;
        const float* wk = &Wqs[k * 270];
        for (int c = 0; c < 10; ++c) {
            const float* wc = wk + c * 27;
            float q[8];
            #pragma unroll
            for (int j = 0; j < 8; ++j) q[j] = 0.f;
            #pragma unroll
            for (int dy = 0; dy < 3; ++dy)
                #pragma unroll
                for (int dx = 0; dx < 3; ++dx) {
                    float w0 = wc[dy * 3 + dx];
                    float w1 = wc[9  + dy * 3 + dx];
                    float w2 = wc[18 + dy * 3 + dx];
                    #pragma unroll
                    for (int j = 0; j < 8; ++j)
                        q[j] += w0 * am[dy][dx + j] + w1 * ar[dy][dx + j] + w2 * av[dy][dx + j];
                }
            #pragma unroll
            for (int j = 0; j < 8; ++j) vm[j] = fmaxf(vm[j], q[j]);
        }
        #pragma unroll
        for (int j = 0; j < 8; ++j) {
            vnxt[(brow + 1) * 66 + bc0 + 1 + j] = vm[j];
            sB[brow * 64 + bc0 + j] += vm[j];
        }
        __syncthreads();
    }
    // v_final = sB/16 into vB (its zero border is intact)
    #pragma unroll
    for (int j = 0; j < 8; ++j)
        vB[(brow + 1) * 66 + bc0 + 1 + j] = sB[brow * 64 + bc0 + j] * 0.0625f;
    __syncthreads();

    // P8: final conv with conv_q_ws[15]; accumulate BN stats; gather q at (S1,S2)
    {
        float av[3][10];
        #pragma unroll
        for (int dy = 0; dy < 3; ++dy)
            #pragma unroll
            for (int dx = 0; dx < 10; ++dx)
                av[dy][dx] = vB[(brow + dy) * 66 + bc0 + dx];
        const int s1 = S1[n], s2 = S2[n];
        const bool gat = (brow == s1) && (s2 >= bc0) && (s2 < bc0 + 8);
        float qsum[10], qsq[10];
        const float* wk = &Wqs[15 * 270];
        for (int c = 0; c < 10; ++c) {
            const float* wc = wk + c * 27;
            float q[8];
            #pragma unroll
            for (int j = 0; j < 8; ++j) q[j] = 0.f;
            #pragma unroll
            for (int dy = 0; dy < 3; ++dy)
                #pragma unroll
                for (int dx = 0; dx < 3; ++dx) {
                    float w0 = wc[dy * 3 + dx];
                    float w1 = wc[9  + dy * 3 + dx];
                    float w2 = wc[18 + dy * 3 + dx];
                    #pragma unroll
                    for (int j = 0; j < 8; ++j)
                        q[j] += w0 * am[dy][dx + j] + w1 * ar[dy][dx + j] + w2 * av[dy][dx + j];
                }
            float s = 0.f, ss = 0.f;
            #pragma unroll
            for (int j = 0; j < 8; ++j) { s += q[j]; ss += q[j] * q[j]; }
            qsum[c] = s; qsq[c] = ss;
            if (gat) g_qsel[n][c] = q[s2 - bc0];
        }
        // deterministic block reduction of (sum, sumsq) per channel
        const int lane = tid & 31, wrp = tid >> 5;
        #pragma unroll
        for (int c = 0; c < 10; ++c) {
            float v1 = qsum[c], v2 = qsq[c];
            #pragma unroll
            for (int off = 16; off > 0; off >>= 1) {
                v1 += __shfl_down_sync(0xffffffffu, v1, off);
                v2 += __shfl_down_sync(0xffffffffu, v2, off);
            }
            if (lane == 0) { red[wrp * 20 + c] = v1; red[wrp * 20 + 10 + c] = v2; }
        }
        __syncthreads();
        if (tid < 20) {
            float t = 0.f;
            for (int w = 0; w < 16; ++w) t += red[w * 20 + tid];
            g_pstats[n][tid] = t;
        }
    }
}

__global__ void vin_final_kernel(const float* __restrict__ gamma,
                                 const float* __restrict__ beta,
                                 const float* __restrict__ w1,   // (1,10)
                                 const float* __restrict__ w2,   // (8,10)
                                 float* __restrict__ out)        // (128,8)
{
    __shared__ float meanv[10], scalev[10];
    const int t = threadIdx.x;
    if (t < 10) {
        double S = 0.0, Q = 0.0;
        for (int nn = 0; nn < 128; ++nn) {
            S += (double)g_pstats[nn][t];
            Q += (double)g_pstats[nn][10 + t];
        }
        double m   = S / 524288.0;
        double var = Q / 524288.0 - m * m;
        meanv[t]  = (float)m;
        scalev[t] = (float)(1.0 / sqrt(var + 1e-5));
    }
    __syncthreads();
    // t = image index (128 threads)
    float qn[10];
    #pragma unroll
    for (int c = 0; c < 10; ++c)
        qn[c] = (g_qsel[t][c] - meanv[c]) * scalev[c] * gamma[c] + beta[c];
    float a = 0.f;
    #pragma unroll
    for (int c = 0; c < 10; ++c) a += qn[c] * w1[c];
    a = fmaxf(a, 0.f);
    float b[8], bm = 0.f;
    #pragma unroll
    for (int j = 0; j < 8; ++j) {
        float s = 0.f;
        #pragma unroll
        for (int c = 0; c < 10; ++c) s += qn[c] * w2[j * 10 + c];
        b[j] = fmaxf(s, 0.f);
        bm += b[j];
    }
    bm *= 0.125f;
    #pragma unroll
    for (int j = 0; j < 8; ++j) out[t * 8 + j] = a + b[j] - bm;
}

extern "C" void kernel_launch(void* const* d_in, const int* in_sizes, int n_in,
                              void* d_out, int out_size)
{
    const float* X    = (const float*)d_in[0];
    const int*   S1   = (const int*)  d_in[1];
    const int*   S2   = (const int*)  d_in[2];
    const float* Wh   = (const float*)d_in[3];   // conv_h_w
    const float* Wr   = (const float*)d_in[4];   // conv_r_w
    const float* Wq   = (const float*)d_in[5];   // conv_q_ws
    const float* gam  = (const float*)d_in[6];   // bn_gamma
    const float* bet  = (const float*)d_in[7];   // bn_beta
    const float* w1   = (const float*)d_in[8];   // duel_w1
    const float* w2   = (const float*)d_in[9];   // duel_w2
    const float* Whv  = (const float*)d_in[10];  // vi_conv_h_w
    const float* Wrv  = (const float*)d_in[11];  // vi_conv_r_w
    const float* Wqv  = (const float*)d_in[12];  // vi_conv_q_ws
    float* out = (float*)d_out;

    cudaFuncSetAttribute(vin_main_kernel,
                         cudaFuncAttributeMaxDynamicSharedMemorySize, SMEM_BYTES);

    vin_main_kernel<<<128, NTH, SMEM_BYTES>>>(X, S1, S2, Wh, Wr, Wq, Whv, Wrv, Wqv);
    vin_final_kernel<<<1, 128>>>(gam, bet, w1, w2, out);
}